// round 15
// baseline (speedup 1.0000x reference)
#include <cuda_runtime.h>
#include <cuda_fp16.h>

#define HH 160
#define WW 160
#define DD 96
#define NB 2
#define NC 4
#define BC 8
#define HO 154
#define WO 154
#define DO2 90
#define WIN 7
#define HWP (HH*WW)
#define CH_STRIDE (HH*WW*DD)
#define N_OUT  (BC*HO*WO*DO2)
#define PP (NB*2)                 // 4 channel-pair slabs
#define PLANE (WO*DO2)            // 13860 half2 entries per (h) plane
#define NCHUNK 8
#define CW 20                     // outputs per chunk
#define CITER (CW+6)              // 26 input planes per chunk

#define COV_NORM 1.0208333333333333f
#define CCONST   4.5e-4f
#define INV343   (1.0f/343.0f)

// [f][b][pr][h][w'][d] as half2 (lanes = channel pair)
__device__ __half2 gB2[3*PP*HH*PLANE];
__device__ double g_acc;

__inline__ __device__ __half2 h2bits(unsigned u) { return *reinterpret_cast<__half2*>(&u); }
__inline__ __device__ unsigned bitsh2(__half2 h) { return *reinterpret_cast<unsigned*>(&h); }

// ---- fused pass1+2: sigmoid + D-window + sliding W-window, vector smem ----
// block: 96 threads = one (b,h,chunk) line; grid (8, HH, NB) = 2560 blocks
__global__ __launch_bounds__(96) void k_p12(const float* __restrict__ x,
                                            const int* __restrict__ y) {
    __shared__ uint4 st4[2][DD];        // [buf][d] = {m01, m23, sv, sq} half2 bits
    __shared__ uint4 ringA[7][DD];      // [slot][d] = fields 0..3
    __shared__ uint2 ringB[7][DD];      // [slot][d] = fields 4..5
    int d = threadIdx.x;
    if (blockIdx.x == 0 && blockIdx.y == 0 && blockIdx.z == 0 && d == 0) g_acc = 0.0;
    int chunk = blockIdx.x;
    int h     = blockIdx.y;
    int b     = blockIdx.z;
    int c0 = chunk * CW;

    const int*   yb  = y + ((size_t)(b * HH + h) * WW) * DD + d;
    const float* xb0 = x + ((size_t)(b * 4 * HH + h) * WW) * DD + d;

    #pragma unroll
    for (int s7 = 0; s7 < 7; s7++) {
        ringA[s7][d] = make_uint4(0u, 0u, 0u, 0u);
        ringB[s7][d] = make_uint2(0u, 0u);
    }

    float sums[12];
    #pragma unroll
    for (int i = 0; i < 12; i++) sums[i] = 0.f;

    int slot = 0;
    for (int it = 0; it < CITER; it++) {
        int w  = c0 + it;
        int we = (w < WW) ? w : (WW - 1);   // clamp; clamped results never emitted
        int buf = it & 1;
        int yv = yb[we * DD];
        float x0 = xb0[we * DD];
        float x1 = xb0[we * DD + CH_STRIDE];
        float x2 = xb0[we * DD + 2 * CH_STRIDE];
        float x3 = xb0[we * DD + 3 * CH_STRIDE];
        float xv = (yv == 0) ? x0 : (yv == 1) ? x1 : (yv == 2) ? x2 : x3;
        float sv = __fdividef(1.f, 1.f + __expf(-xv));
        unsigned m01u = (yv == 0) ? 0x00003C00u : (yv == 1) ? 0x3C000000u : 0u;
        unsigned m23u = (yv == 2) ? 0x00003C00u : (yv == 3) ? 0x3C000000u : 0u;
        __half2 svh = __float2half2_rn(sv);
        __half2 sqh = __float2half2_rn(sv * sv);
        st4[buf][d] = make_uint4(m01u, m23u, bitsh2(svh), bitsh2(sqh));
        __syncthreads();

        if (d < DO2) {
            __half2 z = __float2half2_rn(0.f);
            __half2 a0 = z, a1 = z, a2 = z, a3 = z, a4 = z, a5 = z;
            #pragma unroll
            for (int j = 0; j < WIN; j++) {
                uint4 v = st4[buf][d + j];
                __half2 m01 = h2bits(v.x);
                __half2 m23 = h2bits(v.y);
                __half2 sh  = h2bits(v.z);
                __half2 qh  = h2bits(v.w);
                a0 = __hadd2(a0, m01);
                a1 = __hadd2(a1, m23);
                a2 = __hfma2(m01, sh, a2);
                a3 = __hfma2(m23, sh, a3);
                a4 = __hfma2(m01, qh, a4);
                a5 = __hfma2(m23, qh, a5);
            }
            uint4 oA = ringA[slot][d];
            uint2 oB = ringB[slot][d];
            float2 nn, oo;
            nn = __half22float2(a0); oo = __half22float2(h2bits(oA.x));
            sums[0]  += nn.x - oo.x; sums[1]  += nn.y - oo.y;
            nn = __half22float2(a1); oo = __half22float2(h2bits(oA.y));
            sums[2]  += nn.x - oo.x; sums[3]  += nn.y - oo.y;
            nn = __half22float2(a2); oo = __half22float2(h2bits(oA.z));
            sums[4]  += nn.x - oo.x; sums[5]  += nn.y - oo.y;
            nn = __half22float2(a3); oo = __half22float2(h2bits(oA.w));
            sums[6]  += nn.x - oo.x; sums[7]  += nn.y - oo.y;
            nn = __half22float2(a4); oo = __half22float2(h2bits(oB.x));
            sums[8]  += nn.x - oo.x; sums[9]  += nn.y - oo.y;
            nn = __half22float2(a5); oo = __half22float2(h2bits(oB.y));
            sums[10] += nn.x - oo.x; sums[11] += nn.y - oo.y;
            ringA[slot][d] = make_uint4(bitsh2(a0), bitsh2(a1), bitsh2(a2), bitsh2(a3));
            ringB[slot][d] = make_uint2(bitsh2(a4), bitsh2(a5));

            int wp = w - 6;
            if (it >= 6 && wp < WO) {
                size_t off = (size_t)h * PLANE + wp * DO2 + d;
                #pragma unroll
                for (int f = 0; f < 3; f++)
                    #pragma unroll
                    for (int pr = 0; pr < 2; pr++) {
                        int p = f * 2 + pr;
                        gB2[((size_t)(f * NB + b) * 2 + pr) * (HH * PLANE) + off] =
                            __floats2half2_rn(sums[p * 2], sums[p * 2 + 1]);
                    }
            }
        }
        slot = (slot == 6) ? 0 : slot + 1;
    }
}

__inline__ __device__ float warpReduceSum(float v) {
    #pragma unroll
    for (int o = 16; o > 0; o >>= 1) v += __shfl_down_sync(0xffffffffu, v, o);
    return v;
}

__inline__ __device__ float svalue(float s1, float s2, float s3) {
    float Sx  = s2 + 0.5f  * (343.f - s1);
    float Sxx = s3 + 0.25f * (343.f - s1);
    float ux = Sx * INV343, uy = s1 * INV343;
    float vx  = COV_NORM * (Sxx * INV343 - ux * ux);
    float vy  = COV_NORM * (s1  * INV343 - uy * uy);
    float vxy = COV_NORM * (s2  * INV343 - ux * uy);
    return __fdividef(vxy + CCONST, vx * vy + CCONST);
}

// ---- pass3: H-window, half2 (lanes = channel pair), 3 h-segments ----
__global__ __launch_bounds__(256) void k_p3() {
    int tid = threadIdx.x;
    int j   = blockIdx.x * 256 + tid;    // over PLANE = 13860
    int seg = blockIdx.y;
    int bp  = blockIdx.z;                // 0..3 = b*2+pr
    int h0   = seg * 52;
    int outs = (seg == 2) ? 50 : 52;
    int planes = outs + 6;
    float2 local = {0.f, 0.f};

    if (j < PLANE) {
        const __half2* P0 = gB2 + (size_t)(0 * PP + bp) * (HH * PLANE) + j;
        const __half2* P1 = gB2 + (size_t)(1 * PP + bp) * (HH * PLANE) + j;
        const __half2* P2 = gB2 + (size_t)(2 * PP + bp) * (HH * PLANE) + j;
        const int HS = PLANE;

        float2 r1[7], r2[7], r3[7];
        float2 s1 = {0,0}, s2 = {0,0}, s3 = {0,0};

        #pragma unroll
        for (int k = 0; k < 7; k++) {
            int h = h0 + k;
            float2 w1 = __half22float2(P0[(size_t)h * HS]);
            float2 w2 = __half22float2(P1[(size_t)h * HS]);
            float2 w3 = __half22float2(P2[(size_t)h * HS]);
            s1.x += w1.x; s1.y += w1.y; r1[k] = w1;
            s2.x += w2.x; s2.y += w2.y; r2[k] = w2;
            s3.x += w3.x; s3.y += w3.y; r3[k] = w3;
        }
        local.x += svalue(s1.x, s2.x, s3.x);
        local.y += svalue(s1.y, s2.y, s3.y);

        int nfull = (planes - 7) / 7;
        int rem   = (planes - 7) % 7;
        int h = h0 + 7;
        for (int g = 0; g < nfull; g++, h += 7) {
            #pragma unroll
            for (int k = 0; k < 7; k++) {
                float2 w1 = __half22float2(P0[(size_t)(h + k) * HS]);
                float2 w2 = __half22float2(P1[(size_t)(h + k) * HS]);
                float2 w3 = __half22float2(P2[(size_t)(h + k) * HS]);
                s1.x += w1.x - r1[k].x; s1.y += w1.y - r1[k].y; r1[k] = w1;
                s2.x += w2.x - r2[k].x; s2.y += w2.y - r2[k].y; r2[k] = w2;
                s3.x += w3.x - r3[k].x; s3.y += w3.y - r3[k].y; r3[k] = w3;
                local.x += svalue(s1.x, s2.x, s3.x);
                local.y += svalue(s1.y, s2.y, s3.y);
            }
        }
        #pragma unroll
        for (int k = 0; k < 6; k++) {
            if (k < rem) {
                float2 w1 = __half22float2(P0[(size_t)(h + k) * HS]);
                float2 w2 = __half22float2(P1[(size_t)(h + k) * HS]);
                float2 w3 = __half22float2(P2[(size_t)(h + k) * HS]);
                s1.x += w1.x - r1[k].x; s1.y += w1.y - r1[k].y; r1[k] = w1;
                s2.x += w2.x - r2[k].x; s2.y += w2.y - r2[k].y; r2[k] = w2;
                s3.x += w3.x - r3[k].x; s3.y += w3.y - r3[k].y; r3[k] = w3;
                local.x += svalue(s1.x, s2.x, s3.x);
                local.y += svalue(s1.y, s2.y, s3.y);
            }
        }
    }

    __shared__ float red[8];
    float v = warpReduceSum(local.x + local.y);
    if ((tid & 31) == 0) red[tid >> 5] = v;
    __syncthreads();
    if (tid < 32) {
        v = (tid < 8) ? red[tid] : 0.f;
        v = warpReduceSum(v);
        if (tid == 0) atomicAdd(&g_acc, (double)v);
    }
}

__global__ void k_final(float* out) {
    out[0] = 1.0f - (float)(g_acc * (1.0 / (double)N_OUT));
}

extern "C" void kernel_launch(void* const* d_in, const int* in_sizes, int n_in,
                              void* d_out, int out_size) {
    const float* x = (const float*)d_in[0];
    const int* y = (const int*)d_in[1];
    float* out = (float*)d_out;

    {
        dim3 grid(NCHUNK, HH, NB);              // 2560 blocks x 96 thr
        k_p12<<<grid, 96>>>(x, y);
    }
    {
        dim3 grid((PLANE + 255) / 256, 3, PP);  // 55 x 3 x 4 = 660 blocks
        k_p3<<<grid, 256>>>();
    }
    k_final<<<1, 1>>>(out);
}

// round 16
// speedup vs baseline: 1.3650x; 1.3650x over previous
#include <cuda_runtime.h>
#include <cuda_fp16.h>

#define HH 160
#define WW 160
#define DD 96
#define NB 2
#define NC 4
#define BC 8
#define HO 154
#define WO 154
#define DO2 90
#define WIN 7
#define HWP (HH*WW)
#define CH_STRIDE (HH*WW*DD)
#define N_OUT  (BC*HO*WO*DO2)
#define PP (NB*2)                 // 4 channel-pair slabs
#define PLANE (WO*DO2)            // 13860 half2 entries per (h) plane
#define NCHUNK 8
#define CW 20                     // outputs per chunk
#define CITER (CW+6)              // 26 input planes per chunk

#define COV_NORM 1.0208333333333333f
#define CCONST   4.5e-4f
#define INV343   (1.0f/343.0f)

// [f][b][pr][h][w'][d] as half2 (lanes = channel pair)
__device__ __half2 gB2[3*PP*HH*PLANE];
__device__ double g_acc;

__inline__ __device__ __half2 h2bits(unsigned u) { return *reinterpret_cast<__half2*>(&u); }
__inline__ __device__ unsigned bitsh2(__half2 h) { return *reinterpret_cast<unsigned*>(&h); }

// ---- fused pass1+2: prefetched sigmoid + D-window + sliding W-window ----
// block: 96 threads = one (b,h,chunk) line; grid (8, HH, NB) = 2560 blocks
__global__ __launch_bounds__(96) void k_p12(const float* __restrict__ x,
                                            const int* __restrict__ y) {
    __shared__ uint4 st4[2][DD];        // [buf][d] = {m01, m23, sv, sq} half2 bits
    __shared__ uint4 ringA[7][DD];      // [slot][d] = fields 0..3
    __shared__ uint2 ringB[7][DD];      // [slot][d] = fields 4..5
    int d = threadIdx.x;
    if (blockIdx.x == 0 && blockIdx.y == 0 && blockIdx.z == 0 && d == 0) g_acc = 0.0;
    int chunk = blockIdx.x;
    int h     = blockIdx.y;
    int b     = blockIdx.z;
    int c0 = chunk * CW;

    const int*   yp = y + ((size_t)(b * HH + h) * WW + c0) * DD + d;
    const float* xp = x + ((size_t)(b * 4 * HH + h) * WW + c0) * DD + d;

    #pragma unroll
    for (int s7 = 0; s7 < 7; s7++) {
        ringA[s7][d] = make_uint4(0u, 0u, 0u, 0u);
        ringB[s7][d] = make_uint2(0u, 0u);
    }

    float sums[12];
    #pragma unroll
    for (int i = 0; i < 12; i++) sums[i] = 0.f;

    // 6 emit base pointers (advance shared offset by DO2 per emit)
    __half2* eb[6];
    {
        size_t off0 = (size_t)h * PLANE + (size_t)c0 * DO2 + d;
        #pragma unroll
        for (int f = 0; f < 3; f++)
            #pragma unroll
            for (int pr = 0; pr < 2; pr++)
                eb[f * 2 + pr] = gB2 + ((size_t)(f * NB + b) * 2 + pr) * (HH * PLANE) + off0;
    }
    int eoff = 0;

    // prefetch plane 0
    int   pyv = yp[0];
    float px0 = xp[0];
    float px1 = xp[CH_STRIDE];
    float px2 = xp[2 * CH_STRIDE];
    float px3 = xp[3 * CH_STRIDE];

    int slot = 0;
    for (int it = 0; it < CITER; it++) {
        // current plane from prefetch regs
        int   yv = pyv;
        float x0 = px0, x1 = px1, x2 = px2, x3 = px3;

        float xv = (yv == 0) ? x0 : (yv == 1) ? x1 : (yv == 2) ? x2 : x3;
        float sv = __fdividef(1.f, 1.f + __expf(-xv));
        unsigned m01u = (yv == 0) ? 0x00003C00u : (yv == 1) ? 0x3C000000u : 0u;
        unsigned m23u = (yv == 2) ? 0x00003C00u : (yv == 3) ? 0x3C000000u : 0u;
        int buf = it & 1;
        st4[buf][d] = make_uint4(m01u, m23u,
                                 bitsh2(__float2half2_rn(sv)),
                                 bitsh2(__float2half2_rn(sv * sv)));

        // prefetch next plane (skip => register reuse == old clamp semantics)
        int wn = c0 + it + 1;
        if (wn < WW && it < CITER - 1) {
            yp += DD; xp += DD;
            pyv = yp[0];
            px0 = xp[0];
            px1 = xp[CH_STRIDE];
            px2 = xp[2 * CH_STRIDE];
            px3 = xp[3 * CH_STRIDE];
        }
        __syncthreads();

        if (d < DO2) {
            __half2 z = __float2half2_rn(0.f);
            __half2 a0 = z, a1 = z, a2 = z, a3 = z, a4 = z, a5 = z;
            #pragma unroll
            for (int j = 0; j < WIN; j++) {
                uint4 v = st4[buf][d + j];
                __half2 m01 = h2bits(v.x);
                __half2 m23 = h2bits(v.y);
                __half2 sh  = h2bits(v.z);
                __half2 qh  = h2bits(v.w);
                a0 = __hadd2(a0, m01);
                a1 = __hadd2(a1, m23);
                a2 = __hfma2(m01, sh, a2);
                a3 = __hfma2(m23, sh, a3);
                a4 = __hfma2(m01, qh, a4);
                a5 = __hfma2(m23, qh, a5);
            }
            uint4 oA = ringA[slot][d];
            uint2 oB = ringB[slot][d];
            float2 nn, oo;
            nn = __half22float2(a0); oo = __half22float2(h2bits(oA.x));
            sums[0]  += nn.x - oo.x; sums[1]  += nn.y - oo.y;
            nn = __half22float2(a1); oo = __half22float2(h2bits(oA.y));
            sums[2]  += nn.x - oo.x; sums[3]  += nn.y - oo.y;
            nn = __half22float2(a2); oo = __half22float2(h2bits(oA.z));
            sums[4]  += nn.x - oo.x; sums[5]  += nn.y - oo.y;
            nn = __half22float2(a3); oo = __half22float2(h2bits(oA.w));
            sums[6]  += nn.x - oo.x; sums[7]  += nn.y - oo.y;
            nn = __half22float2(a4); oo = __half22float2(h2bits(oB.x));
            sums[8]  += nn.x - oo.x; sums[9]  += nn.y - oo.y;
            nn = __half22float2(a5); oo = __half22float2(h2bits(oB.y));
            sums[10] += nn.x - oo.x; sums[11] += nn.y - oo.y;
            ringA[slot][d] = make_uint4(bitsh2(a0), bitsh2(a1), bitsh2(a2), bitsh2(a3));
            ringB[slot][d] = make_uint2(bitsh2(a4), bitsh2(a5));

            if (it >= 6 && (c0 + it - 6) < WO) {
                #pragma unroll
                for (int p = 0; p < 6; p++)
                    eb[p][eoff] = __floats2half2_rn(sums[p * 2], sums[p * 2 + 1]);
                eoff += DO2;
            }
        }
        slot = (slot == 6) ? 0 : slot + 1;
    }
}

__inline__ __device__ float warpReduceSum(float v) {
    #pragma unroll
    for (int o = 16; o > 0; o >>= 1) v += __shfl_down_sync(0xffffffffu, v, o);
    return v;
}

__inline__ __device__ float svalue(float s1, float s2, float s3) {
    float Sx  = s2 + 0.5f  * (343.f - s1);
    float Sxx = s3 + 0.25f * (343.f - s1);
    float ux = Sx * INV343, uy = s1 * INV343;
    float vx  = COV_NORM * (Sxx * INV343 - ux * ux);
    float vy  = COV_NORM * (s1  * INV343 - uy * uy);
    float vxy = COV_NORM * (s2  * INV343 - ux * uy);
    return __fdividef(vxy + CCONST, vx * vy + CCONST);
}

// ---- pass3: H-window, half2 (lanes = channel pair), 3 h-segments ----
__global__ __launch_bounds__(256) void k_p3() {
    int tid = threadIdx.x;
    int j   = blockIdx.x * 256 + tid;    // over PLANE = 13860
    int seg = blockIdx.y;
    int bp  = blockIdx.z;                // 0..3 = b*2+pr
    int h0   = seg * 52;
    int outs = (seg == 2) ? 50 : 52;
    int planes = outs + 6;
    float2 local = {0.f, 0.f};

    if (j < PLANE) {
        const __half2* P0 = gB2 + (size_t)(0 * PP + bp) * (HH * PLANE) + j;
        const __half2* P1 = gB2 + (size_t)(1 * PP + bp) * (HH * PLANE) + j;
        const __half2* P2 = gB2 + (size_t)(2 * PP + bp) * (HH * PLANE) + j;
        const int HS = PLANE;

        float2 r1[7], r2[7], r3[7];
        float2 s1 = {0,0}, s2 = {0,0}, s3 = {0,0};

        #pragma unroll
        for (int k = 0; k < 7; k++) {
            int h = h0 + k;
            float2 w1 = __half22float2(P0[(size_t)h * HS]);
            float2 w2 = __half22float2(P1[(size_t)h * HS]);
            float2 w3 = __half22float2(P2[(size_t)h * HS]);
            s1.x += w1.x; s1.y += w1.y; r1[k] = w1;
            s2.x += w2.x; s2.y += w2.y; r2[k] = w2;
            s3.x += w3.x; s3.y += w3.y; r3[k] = w3;
        }
        local.x += svalue(s1.x, s2.x, s3.x);
        local.y += svalue(s1.y, s2.y, s3.y);

        int nfull = (planes - 7) / 7;
        int rem   = (planes - 7) % 7;
        int h = h0 + 7;
        for (int g = 0; g < nfull; g++, h += 7) {
            #pragma unroll
            for (int k = 0; k < 7; k++) {
                float2 w1 = __half22float2(P0[(size_t)(h + k) * HS]);
                float2 w2 = __half22float2(P1[(size_t)(h + k) * HS]);
                float2 w3 = __half22float2(P2[(size_t)(h + k) * HS]);
                s1.x += w1.x - r1[k].x; s1.y += w1.y - r1[k].y; r1[k] = w1;
                s2.x += w2.x - r2[k].x; s2.y += w2.y - r2[k].y; r2[k] = w2;
                s3.x += w3.x - r3[k].x; s3.y += w3.y - r3[k].y; r3[k] = w3;
                local.x += svalue(s1.x, s2.x, s3.x);
                local.y += svalue(s1.y, s2.y, s3.y);
            }
        }
        #pragma unroll
        for (int k = 0; k < 6; k++) {
            if (k < rem) {
                float2 w1 = __half22float2(P0[(size_t)(h + k) * HS]);
                float2 w2 = __half22float2(P1[(size_t)(h + k) * HS]);
                float2 w3 = __half22float2(P2[(size_t)(h + k) * HS]);
                s1.x += w1.x - r1[k].x; s1.y += w1.y - r1[k].y; r1[k] = w1;
                s2.x += w2.x - r2[k].x; s2.y += w2.y - r2[k].y; r2[k] = w2;
                s3.x += w3.x - r3[k].x; s3.y += w3.y - r3[k].y; r3[k] = w3;
                local.x += svalue(s1.x, s2.x, s3.x);
                local.y += svalue(s1.y, s2.y, s3.y);
            }
        }
    }

    __shared__ float red[8];
    float v = warpReduceSum(local.x + local.y);
    if ((tid & 31) == 0) red[tid >> 5] = v;
    __syncthreads();
    if (tid < 32) {
        v = (tid < 8) ? red[tid] : 0.f;
        v = warpReduceSum(v);
        if (tid == 0) atomicAdd(&g_acc, (double)v);
    }
}

__global__ void k_final(float* out) {
    out[0] = 1.0f - (float)(g_acc * (1.0 / (double)N_OUT));
}

extern "C" void kernel_launch(void* const* d_in, const int* in_sizes, int n_in,
                              void* d_out, int out_size) {
    const float* x = (const float*)d_in[0];
    const int* y = (const int*)d_in[1];
    float* out = (float*)d_out;

    {
        dim3 grid(NCHUNK, HH, NB);              // 2560 blocks x 96 thr
        k_p12<<<grid, 96>>>(x, y);
    }
    {
        dim3 grid((PLANE + 255) / 256, 3, PP);  // 55 x 3 x 4 = 660 blocks
        k_p3<<<grid, 256>>>();
    }
    k_final<<<1, 1>>>(out);
}